// round 1
// baseline (speedup 1.0000x reference)
#include <cuda_runtime.h>
#include <cuda_bf16.h>

#define NBINS   256
#define LOG_HW  20                 // pixels per image = 1<<20
#define HW      (1 << LOG_HW)
#define MAXIMG  64
#define BPI     64                 // histogram blocks per image

// ---------------- scratch (device globals; no allocations allowed) ----------
__device__ unsigned g_min_u;
__device__ unsigned g_max_u;
__device__ unsigned g_hist[MAXIMG * NBINS];
__device__ float    g_thr[MAXIMG];

// ordered-uint encoding: unsigned compare == float compare
__device__ __forceinline__ unsigned enc_f(float f) {
    unsigned u = __float_as_uint(f);
    return (u & 0x80000000u) ? ~u : (u | 0x80000000u);
}
__device__ __forceinline__ float dec_f(unsigned k) {
    return (k & 0x80000000u) ? __uint_as_float(k ^ 0x80000000u)
                             : __uint_as_float(~k);
}

// ---------------- K0: reset scratch (must run every launch: graph replays) --
__global__ void k_init() {
    g_hist[blockIdx.x * NBINS + threadIdx.x] = 0u;
    if (blockIdx.x == 0 && threadIdx.x == 0) {
        g_min_u = 0xFFFFFFFFu;   // +inf key
        g_max_u = 0u;            // -inf key
    }
}

// ---------------- K1: global min/max ----------------------------------------
__global__ void k_minmax(const float4* __restrict__ x, long long n4) {
    float mn = __int_as_float(0x7f800000);   // +inf
    float mx = __int_as_float(0xff800000);   // -inf
    long long i = (long long)blockIdx.x * blockDim.x + threadIdx.x;
    long long stride = (long long)gridDim.x * blockDim.x;
    for (; i < n4; i += stride) {
        float4 v = x[i];
        mn = fminf(mn, fminf(fminf(v.x, v.y), fminf(v.z, v.w)));
        mx = fmaxf(mx, fmaxf(fmaxf(v.x, v.y), fmaxf(v.z, v.w)));
    }
    // warp reduce
    #pragma unroll
    for (int o = 16; o; o >>= 1) {
        mn = fminf(mn, __shfl_down_sync(0xFFFFFFFFu, mn, o));
        mx = fmaxf(mx, __shfl_down_sync(0xFFFFFFFFu, mx, o));
    }
    __shared__ float smn[8], smx[8];
    int wid = threadIdx.x >> 5, lane = threadIdx.x & 31;
    if (lane == 0) { smn[wid] = mn; smx[wid] = mx; }
    __syncthreads();
    if (threadIdx.x == 0) {
        int nw = (blockDim.x + 31) >> 5;
        for (int w = 1; w < nw; ++w) {
            mn = fminf(mn, smn[w]);
            mx = fmaxf(mx, smx[w]);
        }
        atomicMin(&g_min_u, enc_f(mn));
        atomicMax(&g_max_u, enc_f(mx));
    }
}

// ---------------- K2: per-image histograms ----------------------------------
__global__ void __launch_bounds__(256) k_hist(const float* __restrict__ x) {
    __shared__ unsigned sh[8 * NBINS];     // per-warp sub-histograms
    for (int i = threadIdx.x; i < 8 * NBINS; i += 256) sh[i] = 0u;
    __syncthreads();

    float mn = dec_f(g_min_u);
    float mx = dec_f(g_max_u);
    // match reference float32: scale = nbins / (mx - mn), no FMA contraction
    float scale = __fdiv_rn(256.0f, __fsub_rn(mx, mn));

    int img   = blockIdx.x >> 6;           // / BPI
    int chunk = blockIdx.x & (BPI - 1);
    const float4* p = (const float4*)x + ((long long)img << (LOG_HW - 2))
                                       + ((long long)chunk << (LOG_HW - 2 - 6));
    unsigned* mysh = &sh[(threadIdx.x >> 5) << 8];

    const int n4_chunk = HW / 4 / BPI;     // 4096 float4 per block
    for (int i = threadIdx.x; i < n4_chunk; i += 256) {
        float4 v = p[i];
        int i0 = (int)floorf(__fmul_rn(__fsub_rn(v.x, mn), scale));
        int i1 = (int)floorf(__fmul_rn(__fsub_rn(v.y, mn), scale));
        int i2 = (int)floorf(__fmul_rn(__fsub_rn(v.z, mn), scale));
        int i3 = (int)floorf(__fmul_rn(__fsub_rn(v.w, mn), scale));
        i0 = min(max(i0, 0), 255); i1 = min(max(i1, 0), 255);
        i2 = min(max(i2, 0), 255); i3 = min(max(i3, 0), 255);
        atomicAdd(&mysh[i0], 1u);
        atomicAdd(&mysh[i1], 1u);
        atomicAdd(&mysh[i2], 1u);
        atomicAdd(&mysh[i3], 1u);
    }
    __syncthreads();

    int b = threadIdx.x;                   // one bin per thread
    unsigned s = sh[b] + sh[256 + b] + sh[512 + b] + sh[768 + b]
               + sh[1024 + b] + sh[1280 + b] + sh[1536 + b] + sh[1792 + b];
    if (s) atomicAdd(&g_hist[img * NBINS + b], s);
}

// ---------------- K3: per-image Otsu (emulates reference fp32 arithmetic) ---
__global__ void k_otsu(float* __restrict__ out_thr) {
    __shared__ float P[NBINS];
    __shared__ float W[NBINS];
    __shared__ float S[NBINS];
    int img = blockIdx.x;
    for (int i = threadIdx.x; i < NBINS; i += blockDim.x)
        P[i] = __fdiv_rn((float)g_hist[img * NBINS + i], (float)HW); // /2^20: exact
    __syncthreads();
    if (threadIdx.x == 0) {
        // sequential float32 cumsums, mirroring jnp.cumsum order
        float w = 0.0f, s = 0.0f;
        for (int i = 0; i < NBINS; ++i) {
            w = __fadd_rn(w, P[i]);
            s = __fadd_rn(s, __fmul_rn(P[i], (float)i));
            W[i] = w; S[i] = s;
        }
        float total = S[NBINS - 1];
        float best = __int_as_float(0xff800000);   // -inf
        int   bt = 0;
        bool  anyv = false;
        for (int t = 0; t < NBINS; ++t) {
            float wb = W[t];
            float wf = __fsub_rn(1.0f, wb);
            float sb = S[t];
            float sf = __fsub_rn(total, sb);
            bool valid = (wb > 0.0f) && (wf > 0.0f);
            float mb = __fdiv_rn(sb, (wb > 0.0f) ? wb : 1.0f);
            float mf = __fdiv_rn(sf, (wf > 0.0f) ? wf : 1.0f);
            float d  = __fsub_rn(mb, mf);
            float iv = valid ? __fmul_rn(__fmul_rn(wb, wf), __fmul_rn(d, d))
                             : __int_as_float(0xff800000);
            if (iv > best) { best = iv; bt = t; }  // strict >: first max, like argmax
            anyv = anyv || valid;
        }
        float mn = dec_f(g_min_u);
        float mx = dec_f(g_max_u);
        int k = min(bt + 1, NBINS - 1);
        // edges = linspace(mn, mx, 256): mn + k * (mx-mn)/255 in float32
        float delta = __fdiv_rn(__fsub_rn(mx, mn), (float)(NBINS - 1));
        float thr = anyv ? __fadd_rn(mn, __fmul_rn((float)k, delta)) : 0.0f;
        g_thr[img]   = thr;
        out_thr[img] = thr;
    }
}

// ---------------- K4: apply threshold ---------------------------------------
__global__ void __launch_bounds__(256) k_apply(const float4* __restrict__ x,
                                               float4* __restrict__ out,
                                               long long n4) {
    long long i = (long long)blockIdx.x * blockDim.x + threadIdx.x;
    long long stride = (long long)gridDim.x * blockDim.x;
    for (; i < n4; i += stride) {
        float4 v = x[i];
        float thr = g_thr[i >> (LOG_HW - 2)];
        v.x = (v.x <= thr) ? 0.0f : v.x;
        v.y = (v.y <= thr) ? 0.0f : v.y;
        v.z = (v.z <= thr) ? 0.0f : v.z;
        v.w = (v.w <= thr) ? 0.0f : v.w;
        out[i] = v;
    }
}

// ---------------- launch -----------------------------------------------------
extern "C" void kernel_launch(void* const* d_in, const int* in_sizes, int n_in,
                              void* d_out, int out_size) {
    const float* x = (const float*)d_in[0];
    long long npx = (long long)in_sizes[0];      // 48 * 2^20
    int n = (int)(npx >> LOG_HW);                // images
    long long n4 = npx >> 2;
    float* out = (float*)d_out;

    k_init  <<<n, NBINS>>>();
    k_minmax<<<1184, 256>>>((const float4*)x, n4);
    k_hist  <<<n * BPI, 256>>>(x);
    k_otsu  <<<n, 64>>>(out + npx);
    k_apply <<<12288, 256>>>((const float4*)x, (float4*)out, n4);
}

// round 2
// speedup vs baseline: 1.0801x; 1.0801x over previous
#include <cuda_runtime.h>
#include <cuda_bf16.h>

#define NBINS   256
#define LOG_HW  20                 // pixels per image = 1<<20
#define HW      (1 << LOG_HW)
#define MAXIMG  64
#define BPI     64                 // histogram blocks per image

// ---------------- scratch (device globals; no allocations allowed) ----------
__device__ unsigned g_min_u;
__device__ unsigned g_max_u;
__device__ unsigned g_part[MAXIMG * BPI * NBINS];  // per-block partial hists (16 MiB)
__device__ float    g_thr[MAXIMG];

// ordered-uint encoding: unsigned compare == float compare
__device__ __forceinline__ unsigned enc_f(float f) {
    unsigned u = __float_as_uint(f);
    return (u & 0x80000000u) ? ~u : (u | 0x80000000u);
}
__device__ __forceinline__ float dec_f(unsigned k) {
    return (k & 0x80000000u) ? __uint_as_float(k ^ 0x80000000u)
                             : __uint_as_float(~k);
}

// ---------------- K0: reset min/max keys (graph replays need this) ----------
__global__ void k_init() {
    if (threadIdx.x == 0) {
        g_min_u = 0xFFFFFFFFu;   // +inf key
        g_max_u = 0u;            // -inf key
    }
}

// ---------------- K1: global min/max ----------------------------------------
__global__ void __launch_bounds__(256) k_minmax(const float4* __restrict__ x,
                                                long long n4) {
    float mn = __int_as_float(0x7f800000);   // +inf
    float mx = __int_as_float(0xff800000);   // -inf
    long long i = (long long)blockIdx.x * blockDim.x + threadIdx.x;
    long long stride = (long long)gridDim.x * blockDim.x;
    for (; i < n4; i += stride) {
        float4 v = x[i];
        mn = fminf(mn, fminf(fminf(v.x, v.y), fminf(v.z, v.w)));
        mx = fmaxf(mx, fmaxf(fmaxf(v.x, v.y), fmaxf(v.z, v.w)));
    }
    #pragma unroll
    for (int o = 16; o; o >>= 1) {
        mn = fminf(mn, __shfl_down_sync(0xFFFFFFFFu, mn, o));
        mx = fmaxf(mx, __shfl_down_sync(0xFFFFFFFFu, mx, o));
    }
    __shared__ float smn[8], smx[8];
    int wid = threadIdx.x >> 5, lane = threadIdx.x & 31;
    if (lane == 0) { smn[wid] = mn; smx[wid] = mx; }
    __syncthreads();
    if (threadIdx.x == 0) {
        #pragma unroll
        for (int w = 1; w < 8; ++w) {
            mn = fminf(mn, smn[w]);
            mx = fmaxf(mx, smx[w]);
        }
        atomicMin(&g_min_u, enc_f(mn));
        atomicMax(&g_max_u, enc_f(mx));
    }
}

// ---------------- K2: per-image histograms -> private partial slots ---------
__global__ void __launch_bounds__(256) k_hist(const float* __restrict__ x) {
    __shared__ unsigned sh[8 * NBINS];     // per-warp sub-histograms
    for (int i = threadIdx.x; i < 8 * NBINS; i += 256) sh[i] = 0u;
    __syncthreads();

    float mn = dec_f(g_min_u);
    float mx = dec_f(g_max_u);
    float scale = __fdiv_rn(256.0f, __fsub_rn(mx, mn));  // match ref fp32

    int img   = blockIdx.x >> 6;           // / BPI
    int chunk = blockIdx.x & (BPI - 1);
    const float4* p = (const float4*)x + ((long long)img << (LOG_HW - 2))
                                       + ((long long)chunk << (LOG_HW - 2 - 6));
    unsigned* mysh = &sh[(threadIdx.x >> 5) << 8];

    const int n4_chunk = HW / 4 / BPI;     // 4096 float4 per block
    for (int i = threadIdx.x; i < n4_chunk; i += 256) {
        float4 v = p[i];
        int i0 = (int)floorf(__fmul_rn(__fsub_rn(v.x, mn), scale));
        int i1 = (int)floorf(__fmul_rn(__fsub_rn(v.y, mn), scale));
        int i2 = (int)floorf(__fmul_rn(__fsub_rn(v.z, mn), scale));
        int i3 = (int)floorf(__fmul_rn(__fsub_rn(v.w, mn), scale));
        i0 = min(max(i0, 0), 255); i1 = min(max(i1, 0), 255);
        i2 = min(max(i2, 0), 255); i3 = min(max(i3, 0), 255);
        atomicAdd(&mysh[i0], 1u);
        atomicAdd(&mysh[i1], 1u);
        atomicAdd(&mysh[i2], 1u);
        atomicAdd(&mysh[i3], 1u);
    }
    __syncthreads();

    int b = threadIdx.x;                   // one bin per thread
    unsigned s = sh[b] + sh[256 + b] + sh[512 + b] + sh[768 + b]
               + sh[1024 + b] + sh[1280 + b] + sh[1536 + b] + sh[1792 + b];
    g_part[(long long)blockIdx.x * NBINS + b] = s;   // plain store, no init needed
}

// ---------------- K3: per-image Otsu (parallel divides, serial fp32 cumsum) --
__global__ void __launch_bounds__(256) k_otsu(float* __restrict__ out_thr) {
    __shared__ float P[NBINS];
    __shared__ float W[NBINS];
    __shared__ float S[NBINS];
    __shared__ float s_iv[NBINS];
    __shared__ int   s_anyv;
    int img = blockIdx.x;
    int t = threadIdx.x;

    // sum the 64 per-block partials for this bin (coalesced across threads)
    unsigned cnt = 0u;
    const unsigned* base = &g_part[(long long)img * BPI * NBINS + t];
    #pragma unroll 8
    for (int c = 0; c < BPI; ++c) cnt += base[c * NBINS];
    P[t] = __fmul_rn((float)cnt, 9.5367431640625e-07f);  // * 2^-20, exact
    if (t == 0) s_anyv = 0;
    __syncthreads();

    // sequential float32 cumsums (bit-identical order to jnp.cumsum fp32)
    if (t == 0) {
        float w = 0.0f, s = 0.0f;
        for (int i = 0; i < NBINS; ++i) {
            w = __fadd_rn(w, P[i]);
            s = __fadd_rn(s, __fmul_rn(P[i], (float)i));
            W[i] = w; S[i] = s;
        }
    }
    __syncthreads();

    // parallel inter-class variance per candidate threshold
    float total = S[NBINS - 1];
    float wb = W[t];
    float wf = __fsub_rn(1.0f, wb);
    float sb = S[t];
    float sf = __fsub_rn(total, sb);
    bool valid = (wb > 0.0f) && (wf > 0.0f);
    float mb = __fdiv_rn(sb, (wb > 0.0f) ? wb : 1.0f);
    float mf = __fdiv_rn(sf, (wf > 0.0f) ? wf : 1.0f);
    float d  = __fsub_rn(mb, mf);
    s_iv[t] = valid ? __fmul_rn(__fmul_rn(wb, wf), __fmul_rn(d, d))
                    : __int_as_float(0xff800000);
    if (valid) s_anyv = 1;
    __syncthreads();

    // argmax with first-max (lowest index) tie-break; thread 0 finalizes
    if (t == 0) {
        float best = s_iv[0];
        int bt = 0;
        for (int i = 1; i < NBINS; ++i) {
            float v = s_iv[i];
            if (v > best) { best = v; bt = i; }
        }
        float mn = dec_f(g_min_u);
        float mx = dec_f(g_max_u);
        int k = min(bt + 1, NBINS - 1);
        float delta = __fdiv_rn(__fsub_rn(mx, mn), (float)(NBINS - 1));
        float thr = s_anyv ? __fadd_rn(mn, __fmul_rn((float)k, delta)) : 0.0f;
        g_thr[img]   = thr;
        out_thr[img] = thr;
    }
}

// ---------------- K4: apply threshold ---------------------------------------
__global__ void __launch_bounds__(256) k_apply(const float4* __restrict__ x,
                                               float4* __restrict__ out,
                                               long long n4) {
    long long i = (long long)blockIdx.x * blockDim.x + threadIdx.x;
    long long stride = (long long)gridDim.x * blockDim.x;
    for (; i < n4; i += stride) {
        float4 v = x[i];
        float thr = g_thr[i >> (LOG_HW - 2)];
        v.x = (v.x <= thr) ? 0.0f : v.x;
        v.y = (v.y <= thr) ? 0.0f : v.y;
        v.z = (v.z <= thr) ? 0.0f : v.z;
        v.w = (v.w <= thr) ? 0.0f : v.w;
        out[i] = v;
    }
}

// ---------------- launch -----------------------------------------------------
extern "C" void kernel_launch(void* const* d_in, const int* in_sizes, int n_in,
                              void* d_out, int out_size) {
    const float* x = (const float*)d_in[0];
    long long npx = (long long)in_sizes[0];      // 48 * 2^20
    int n = (int)(npx >> LOG_HW);                // images
    long long n4 = npx >> 2;
    float* out = (float*)d_out;

    k_init  <<<1, 32>>>();
    k_minmax<<<1184, 256>>>((const float4*)x, n4);
    k_hist  <<<n * BPI, 256>>>(x);
    k_otsu  <<<n, NBINS>>>(out + npx);
    k_apply <<<12288, 256>>>((const float4*)x, (float4*)out, n4);
}

// round 3
// speedup vs baseline: 1.1248x; 1.0414x over previous
#include <cuda_runtime.h>
#include <cuda_bf16.h>

#define NBINS   256
#define LOG_HW  20                 // pixels per image = 1<<20
#define HW      (1 << LOG_HW)
#define MAXIMG  64
#define BPI     64                 // histogram blocks per image

// ---------------- scratch (device globals; no allocations allowed) ----------
__device__ unsigned g_min_u;
__device__ unsigned g_max_u;
__device__ unsigned g_hist[MAXIMG * NBINS];
__device__ float    g_thr[MAXIMG];

// ordered-uint encoding: unsigned compare == float compare
__device__ __forceinline__ unsigned enc_f(float f) {
    unsigned u = __float_as_uint(f);
    return (u & 0x80000000u) ? ~u : (u | 0x80000000u);
}
__device__ __forceinline__ float dec_f(unsigned k) {
    return (k & 0x80000000u) ? __uint_as_float(k ^ 0x80000000u)
                             : __uint_as_float(~k);
}

// ---------------- K0: reset keys + zero hist (graph replays) ----------------
__global__ void k_init(int n) {
    if (blockIdx.x < n)
        g_hist[blockIdx.x * NBINS + threadIdx.x] = 0u;
    if (blockIdx.x == 0 && threadIdx.x == 0) {
        g_min_u = 0xFFFFFFFFu;   // +inf key
        g_max_u = 0u;            // -inf key
    }
}

// ---------------- K1: global min/max ----------------------------------------
__global__ void __launch_bounds__(256) k_minmax(const float4* __restrict__ x,
                                                long long n4) {
    float mn = __int_as_float(0x7f800000);   // +inf
    float mx = __int_as_float(0xff800000);   // -inf
    long long i = (long long)blockIdx.x * blockDim.x + threadIdx.x;
    long long stride = (long long)gridDim.x * blockDim.x;
    // batched: 4 independent loads in flight per iteration
    for (; i + 3 * stride < n4; i += 4 * stride) {
        float4 a = x[i];
        float4 b = x[i + stride];
        float4 c = x[i + 2 * stride];
        float4 d = x[i + 3 * stride];
        mn = fminf(mn, fminf(fminf(a.x, a.y), fminf(a.z, a.w)));
        mx = fmaxf(mx, fmaxf(fmaxf(a.x, a.y), fmaxf(a.z, a.w)));
        mn = fminf(mn, fminf(fminf(b.x, b.y), fminf(b.z, b.w)));
        mx = fmaxf(mx, fmaxf(fmaxf(b.x, b.y), fmaxf(b.z, b.w)));
        mn = fminf(mn, fminf(fminf(c.x, c.y), fminf(c.z, c.w)));
        mx = fmaxf(mx, fmaxf(fmaxf(c.x, c.y), fmaxf(c.z, c.w)));
        mn = fminf(mn, fminf(fminf(d.x, d.y), fminf(d.z, d.w)));
        mx = fmaxf(mx, fmaxf(fmaxf(d.x, d.y), fmaxf(d.z, d.w)));
    }
    for (; i < n4; i += stride) {
        float4 v = x[i];
        mn = fminf(mn, fminf(fminf(v.x, v.y), fminf(v.z, v.w)));
        mx = fmaxf(mx, fmaxf(fmaxf(v.x, v.y), fmaxf(v.z, v.w)));
    }
    #pragma unroll
    for (int o = 16; o; o >>= 1) {
        mn = fminf(mn, __shfl_down_sync(0xFFFFFFFFu, mn, o));
        mx = fmaxf(mx, __shfl_down_sync(0xFFFFFFFFu, mx, o));
    }
    __shared__ float smn[8], smx[8];
    int wid = threadIdx.x >> 5, lane = threadIdx.x & 31;
    if (lane == 0) { smn[wid] = mn; smx[wid] = mx; }
    __syncthreads();
    if (threadIdx.x == 0) {
        #pragma unroll
        for (int w = 1; w < 8; ++w) {
            mn = fminf(mn, smn[w]);
            mx = fmaxf(mx, smx[w]);
        }
        atomicMin(&g_min_u, enc_f(mn));
        atomicMax(&g_max_u, enc_f(mx));
    }
}

// ---------------- K2: per-image histograms ----------------------------------
__global__ void __launch_bounds__(256) k_hist(const float* __restrict__ x) {
    __shared__ unsigned sh[8 * NBINS];     // per-warp sub-histograms
    for (int i = threadIdx.x; i < 8 * NBINS; i += 256) sh[i] = 0u;
    __syncthreads();

    float mn = dec_f(g_min_u);
    float mx = dec_f(g_max_u);
    float scale = __fdiv_rn(256.0f, __fsub_rn(mx, mn));  // match ref fp32

    int img   = blockIdx.x >> 6;           // / BPI
    int chunk = blockIdx.x & (BPI - 1);
    const float4* p = (const float4*)x + ((long long)img << (LOG_HW - 2))
                                       + ((long long)chunk << (LOG_HW - 2 - 6));
    unsigned* mysh = &sh[(threadIdx.x >> 5) << 8];

    const int n4_chunk = HW / 4 / BPI;     // 4096 float4 per block
    for (int i = threadIdx.x; i < n4_chunk; i += 256) {
        float4 v = p[i];
        int i0 = (int)floorf(__fmul_rn(__fsub_rn(v.x, mn), scale));
        int i1 = (int)floorf(__fmul_rn(__fsub_rn(v.y, mn), scale));
        int i2 = (int)floorf(__fmul_rn(__fsub_rn(v.z, mn), scale));
        int i3 = (int)floorf(__fmul_rn(__fsub_rn(v.w, mn), scale));
        i0 = min(max(i0, 0), 255); i1 = min(max(i1, 0), 255);
        i2 = min(max(i2, 0), 255); i3 = min(max(i3, 0), 255);
        atomicAdd(&mysh[i0], 1u);
        atomicAdd(&mysh[i1], 1u);
        atomicAdd(&mysh[i2], 1u);
        atomicAdd(&mysh[i3], 1u);
    }
    __syncthreads();

    int b = threadIdx.x;                   // one bin per thread
    unsigned s = sh[b] + sh[256 + b] + sh[512 + b] + sh[768 + b]
               + sh[1024 + b] + sh[1280 + b] + sh[1536 + b] + sh[1792 + b];
    if (s) atomicAdd(&g_hist[img * NBINS + b], s);  // spread-address REDG
}

// ---------------- K3: per-image Otsu ----------------------------------------
__global__ void __launch_bounds__(256) k_otsu(float* __restrict__ out_thr) {
    __shared__ float P[NBINS];
    __shared__ float W[NBINS];
    __shared__ float S[NBINS];
    __shared__ unsigned long long s_key[8];
    int img = blockIdx.x;
    int t = threadIdx.x;

    P[t] = __fmul_rn((float)g_hist[img * NBINS + t],
                     9.5367431640625e-07f);          // * 2^-20, exact
    __syncthreads();

    // sequential float32 cumsums (bit-identical order to jnp.cumsum fp32)
    if (t == 0) {
        float w = 0.0f, s = 0.0f;
        for (int i = 0; i < NBINS; ++i) {
            w = __fadd_rn(w, P[i]);
            s = __fadd_rn(s, __fmul_rn(P[i], (float)i));
            W[i] = w; S[i] = s;
        }
    }
    __syncthreads();

    // parallel inter-class variance per candidate threshold
    float total = S[NBINS - 1];
    float wb = W[t];
    float wf = __fsub_rn(1.0f, wb);
    float sb = S[t];
    float sf = __fsub_rn(total, sb);
    bool valid = (wb > 0.0f) && (wf > 0.0f);
    float mb = __fdiv_rn(sb, (wb > 0.0f) ? wb : 1.0f);
    float mf = __fdiv_rn(sf, (wf > 0.0f) ? wf : 1.0f);
    float d  = __fsub_rn(mb, mf);
    float iv = valid ? __fmul_rn(__fmul_rn(wb, wf), __fmul_rn(d, d))
                     : __int_as_float(0xff800000);
    int anyv = __syncthreads_or(valid ? 1 : 0);

    // parallel argmax, first-max tie-break: larger (255 - t) wins ties
    unsigned long long key =
        ((unsigned long long)enc_f(iv) << 32) | (unsigned)(NBINS - 1 - t);
    #pragma unroll
    for (int o = 16; o; o >>= 1) {
        unsigned long long other = __shfl_down_sync(0xFFFFFFFFu, key, o);
        if (other > key) key = other;
    }
    int wid = t >> 5, lane = t & 31;
    if (lane == 0) s_key[wid] = key;
    __syncthreads();

    if (t == 0) {
        unsigned long long best = s_key[0];
        #pragma unroll
        for (int w = 1; w < 8; ++w)
            if (s_key[w] > best) best = s_key[w];
        int bt = NBINS - 1 - (int)(best & 0xFFFFFFFFu);
        float mn = dec_f(g_min_u);
        float mx = dec_f(g_max_u);
        int k = min(bt + 1, NBINS - 1);
        float delta = __fdiv_rn(__fsub_rn(mx, mn), (float)(NBINS - 1));
        float thr = anyv ? __fadd_rn(mn, __fmul_rn((float)k, delta)) : 0.0f;
        g_thr[img]   = thr;
        out_thr[img] = thr;
    }
}

// ---------------- K4: apply threshold ---------------------------------------
__global__ void __launch_bounds__(256) k_apply(const float4* __restrict__ x,
                                               float4* __restrict__ out,
                                               long long n4) {
    long long i = (long long)blockIdx.x * blockDim.x + threadIdx.x;
    long long stride = (long long)gridDim.x * blockDim.x;
    for (; i < n4; i += stride) {
        float4 v = x[i];
        float thr = g_thr[i >> (LOG_HW - 2)];
        v.x = (v.x <= thr) ? 0.0f : v.x;
        v.y = (v.y <= thr) ? 0.0f : v.y;
        v.z = (v.z <= thr) ? 0.0f : v.z;
        v.w = (v.w <= thr) ? 0.0f : v.w;
        out[i] = v;
    }
}

// ---------------- launch -----------------------------------------------------
extern "C" void kernel_launch(void* const* d_in, const int* in_sizes, int n_in,
                              void* d_out, int out_size) {
    const float* x = (const float*)d_in[0];
    long long npx = (long long)in_sizes[0];      // 48 * 2^20
    int n = (int)(npx >> LOG_HW);                // images
    long long n4 = npx >> 2;
    float* out = (float*)d_out;

    k_init  <<<n, NBINS>>>(n);
    k_minmax<<<1184, 256>>>((const float4*)x, n4);
    k_hist  <<<n * BPI, 256>>>(x);
    k_otsu  <<<n, NBINS>>>(out + npx);
    k_apply <<<12288, 256>>>((const float4*)x, (float4*)out, n4);
}

// round 4
// speedup vs baseline: 1.1491x; 1.0216x over previous
#include <cuda_runtime.h>
#include <cuda_bf16.h>

#define NBINS   256
#define LOG_HW  20                 // pixels per image = 1<<20
#define HW      (1 << LOG_HW)
#define MAXIMG  64
#define BPI     64                 // histogram blocks per image

// ---------------- scratch (device globals; no allocations allowed) ----------
__device__ unsigned g_min_u;
__device__ unsigned g_max_u;
__device__ unsigned g_hist[MAXIMG * NBINS];
__device__ unsigned g_done[MAXIMG];
__device__ float    g_thr[MAXIMG];

// ordered-uint encoding: unsigned compare == float compare
__device__ __forceinline__ unsigned enc_f(float f) {
    unsigned u = __float_as_uint(f);
    return (u & 0x80000000u) ? ~u : (u | 0x80000000u);
}
__device__ __forceinline__ float dec_f(unsigned k) {
    return (k & 0x80000000u) ? __uint_as_float(k ^ 0x80000000u)
                             : __uint_as_float(~k);
}

// ---------------- K0: reset min/max keys only -------------------------------
__global__ void k_init() {
    if (threadIdx.x == 0) {
        g_min_u = 0xFFFFFFFFu;   // +inf key
        g_max_u = 0u;            // -inf key
    }
}

// ---------------- K1: global min/max (+ zero hist/counters for next pass) ---
__global__ void __launch_bounds__(256) k_minmax(const float4* __restrict__ x,
                                                long long n4, int n) {
    // piggyback: zero hist + done counters (consumed only by the NEXT kernel)
    if (blockIdx.x < (unsigned)n)
        g_hist[blockIdx.x * NBINS + threadIdx.x] = 0u;
    if (blockIdx.x == 0 && threadIdx.x < (unsigned)n)
        g_done[threadIdx.x] = 0u;

    float mn = __int_as_float(0x7f800000);   // +inf
    float mx = __int_as_float(0xff800000);   // -inf
    long long i = (long long)blockIdx.x * blockDim.x + threadIdx.x;
    long long stride = (long long)gridDim.x * blockDim.x;
    for (; i + 3 * stride < n4; i += 4 * stride) {
        float4 a = x[i];
        float4 b = x[i + stride];
        float4 c = x[i + 2 * stride];
        float4 d = x[i + 3 * stride];
        mn = fminf(mn, fminf(fminf(a.x, a.y), fminf(a.z, a.w)));
        mx = fmaxf(mx, fmaxf(fmaxf(a.x, a.y), fmaxf(a.z, a.w)));
        mn = fminf(mn, fminf(fminf(b.x, b.y), fminf(b.z, b.w)));
        mx = fmaxf(mx, fmaxf(fmaxf(b.x, b.y), fmaxf(b.z, b.w)));
        mn = fminf(mn, fminf(fminf(c.x, c.y), fminf(c.z, c.w)));
        mx = fmaxf(mx, fmaxf(fmaxf(c.x, c.y), fmaxf(c.z, c.w)));
        mn = fminf(mn, fminf(fminf(d.x, d.y), fminf(d.z, d.w)));
        mx = fmaxf(mx, fmaxf(fmaxf(d.x, d.y), fmaxf(d.z, d.w)));
    }
    for (; i < n4; i += stride) {
        float4 v = x[i];
        mn = fminf(mn, fminf(fminf(v.x, v.y), fminf(v.z, v.w)));
        mx = fmaxf(mx, fmaxf(fmaxf(v.x, v.y), fmaxf(v.z, v.w)));
    }
    #pragma unroll
    for (int o = 16; o; o >>= 1) {
        mn = fminf(mn, __shfl_down_sync(0xFFFFFFFFu, mn, o));
        mx = fmaxf(mx, __shfl_down_sync(0xFFFFFFFFu, mx, o));
    }
    __shared__ float smn[8], smx[8];
    int wid = threadIdx.x >> 5, lane = threadIdx.x & 31;
    if (lane == 0) { smn[wid] = mn; smx[wid] = mx; }
    __syncthreads();
    if (threadIdx.x == 0) {
        #pragma unroll
        for (int w = 1; w < 8; ++w) {
            mn = fminf(mn, smn[w]);
            mx = fmaxf(mx, smx[w]);
        }
        atomicMin(&g_min_u, enc_f(mn));
        atomicMax(&g_max_u, enc_f(mx));
    }
}

// ---------------- K2: per-image histograms + inline Otsu on last block ------
__global__ void __launch_bounds__(256) k_hist(const float* __restrict__ x,
                                              float* __restrict__ out_thr) {
    __shared__ unsigned sh[8 * NBINS];     // per-warp sub-histograms
    for (int i = threadIdx.x; i < 8 * NBINS; i += 256) sh[i] = 0u;
    __syncthreads();

    float mn = dec_f(g_min_u);
    float mx = dec_f(g_max_u);
    float scale = __fdiv_rn(256.0f, __fsub_rn(mx, mn));  // match ref fp32

    int img   = blockIdx.x >> 6;           // / BPI
    int chunk = blockIdx.x & (BPI - 1);
    const float4* p = (const float4*)x + ((long long)img << (LOG_HW - 2))
                                       + ((long long)chunk << (LOG_HW - 2 - 6));
    unsigned* mysh = &sh[(threadIdx.x >> 5) << 8];

    const int n4_chunk = HW / 4 / BPI;     // 4096 float4 per block
    for (int i = threadIdx.x; i < n4_chunk; i += 256) {
        float4 v = p[i];
        int i0 = (int)floorf(__fmul_rn(__fsub_rn(v.x, mn), scale));
        int i1 = (int)floorf(__fmul_rn(__fsub_rn(v.y, mn), scale));
        int i2 = (int)floorf(__fmul_rn(__fsub_rn(v.z, mn), scale));
        int i3 = (int)floorf(__fmul_rn(__fsub_rn(v.w, mn), scale));
        i0 = min(max(i0, 0), 255); i1 = min(max(i1, 0), 255);
        i2 = min(max(i2, 0), 255); i3 = min(max(i3, 0), 255);
        atomicAdd(&mysh[i0], 1u);
        atomicAdd(&mysh[i1], 1u);
        atomicAdd(&mysh[i2], 1u);
        atomicAdd(&mysh[i3], 1u);
    }
    __syncthreads();

    int t = threadIdx.x;                   // one bin per thread
    unsigned s = sh[t] + sh[256 + t] + sh[512 + t] + sh[768 + t]
               + sh[1024 + t] + sh[1280 + t] + sh[1536 + t] + sh[1792 + t];
    if (s) atomicAdd(&g_hist[img * NBINS + t], s);

    // ---- last-block-done: this image's histogram is complete -> Otsu inline
    __threadfence();
    __syncthreads();                       // all threads' hist atomics + fences done
    __shared__ unsigned s_last;
    if (t == 0) s_last = atomicAdd(&g_done[img], 1u);
    __syncthreads();
    if (s_last != BPI - 1) return;         // uniform across block
    __threadfence();                       // acquire side

    __shared__ float P[NBINS];
    __shared__ float W[NBINS];
    __shared__ float S[NBINS];
    __shared__ unsigned long long s_key[8];

    P[t] = __fmul_rn((float)g_hist[img * NBINS + t],
                     9.5367431640625e-07f);          // * 2^-20, exact
    __syncthreads();

    // sequential fp32 cumsums, bit-identical order; float4 loads pipeline LDS
    if (t == 0) {
        float w = 0.0f, sm = 0.0f;
        #pragma unroll
        for (int i = 0; i < NBINS; i += 4) {
            float4 a = *(const float4*)&P[i];
            w = __fadd_rn(w, a.x); sm = __fadd_rn(sm, __fmul_rn(a.x, (float)(i + 0))); W[i + 0] = w; S[i + 0] = sm;
            w = __fadd_rn(w, a.y); sm = __fadd_rn(sm, __fmul_rn(a.y, (float)(i + 1))); W[i + 1] = w; S[i + 1] = sm;
            w = __fadd_rn(w, a.z); sm = __fadd_rn(sm, __fmul_rn(a.z, (float)(i + 2))); W[i + 2] = w; S[i + 2] = sm;
            w = __fadd_rn(w, a.w); sm = __fadd_rn(sm, __fmul_rn(a.w, (float)(i + 3))); W[i + 3] = w; S[i + 3] = sm;
        }
    }
    __syncthreads();

    float total = S[NBINS - 1];
    float wb = W[t];
    float wf = __fsub_rn(1.0f, wb);
    float sb = S[t];
    float sf = __fsub_rn(total, sb);
    bool valid = (wb > 0.0f) && (wf > 0.0f);
    float mb = __fdiv_rn(sb, (wb > 0.0f) ? wb : 1.0f);
    float mf = __fdiv_rn(sf, (wf > 0.0f) ? wf : 1.0f);
    float d  = __fsub_rn(mb, mf);
    float iv = valid ? __fmul_rn(__fmul_rn(wb, wf), __fmul_rn(d, d))
                     : __int_as_float(0xff800000);
    int anyv = __syncthreads_or(valid ? 1 : 0);

    // parallel argmax, first-max tie-break: larger (255 - t) wins ties
    unsigned long long key =
        ((unsigned long long)enc_f(iv) << 32) | (unsigned)(NBINS - 1 - t);
    #pragma unroll
    for (int o = 16; o; o >>= 1) {
        unsigned long long other = __shfl_down_sync(0xFFFFFFFFu, key, o);
        if (other > key) key = other;
    }
    if ((t & 31) == 0) s_key[t >> 5] = key;
    __syncthreads();

    if (t == 0) {
        unsigned long long best = s_key[0];
        #pragma unroll
        for (int w = 1; w < 8; ++w)
            if (s_key[w] > best) best = s_key[w];
        int bt = NBINS - 1 - (int)(best & 0xFFFFFFFFu);
        int k = min(bt + 1, NBINS - 1);
        float delta = __fdiv_rn(__fsub_rn(mx, mn), (float)(NBINS - 1));
        float thr = anyv ? __fadd_rn(mn, __fmul_rn((float)k, delta)) : 0.0f;
        g_thr[img]   = thr;
        out_thr[img] = thr;
    }
}

// ---------------- K3: apply threshold ---------------------------------------
__global__ void __launch_bounds__(256) k_apply(const float4* __restrict__ x,
                                               float4* __restrict__ out,
                                               long long n4) {
    long long i = (long long)blockIdx.x * blockDim.x + threadIdx.x;
    long long stride = (long long)gridDim.x * blockDim.x;
    for (; i < n4; i += stride) {
        float4 v = x[i];
        float thr = g_thr[i >> (LOG_HW - 2)];
        v.x = (v.x <= thr) ? 0.0f : v.x;
        v.y = (v.y <= thr) ? 0.0f : v.y;
        v.z = (v.z <= thr) ? 0.0f : v.z;
        v.w = (v.w <= thr) ? 0.0f : v.w;
        out[i] = v;
    }
}

// ---------------- launch -----------------------------------------------------
extern "C" void kernel_launch(void* const* d_in, const int* in_sizes, int n_in,
                              void* d_out, int out_size) {
    const float* x = (const float*)d_in[0];
    long long npx = (long long)in_sizes[0];      // 48 * 2^20
    int n = (int)(npx >> LOG_HW);                // images
    long long n4 = npx >> 2;
    float* out = (float*)d_out;

    k_init  <<<1, 32>>>();
    k_minmax<<<1184, 256>>>((const float4*)x, n4, n);
    k_hist  <<<n * BPI, 256>>>(x, out + npx);
    k_apply <<<12288, 256>>>((const float4*)x, (float4*)out, n4);
}